// round 11
// baseline (speedup 1.0000x reference)
#include <cuda_runtime.h>
#include <cuda_bf16.h>

#define BATCH 16
#define MP 30      // max people
#define NJ 17      // joints
#define AD 17      // ae tag dim
#define RES 512
#define RR (RES*RES)

#define JPI   (MP * NJ)                 // 510 joints per image
#define ROWP  20                        // padded floats per joint row (80B)
#define EPI   (JPI * AD)                // 8670 gather elements per image
#define GBPI  17                        // gather blocks per image (17*512 >= 8670)
#define GRID_CTAS (BATCH + BATCH * GBPI)   // 16 reduce + 272 gather = 288
#define BT 512

// scratch: masked gathered tags, padded rows: [b*JPI + jl][ROWP]
__device__ __align__(16) float g_scratch[BATCH * JPI * ROWP];
// per-image producer counters (zero-init; reset by consumer each replay)
__device__ unsigned g_done[BATCH];

__global__ __launch_bounds__(BT, 1)
void ae_onekernel(const float* __restrict__ tags,
                  const int*   __restrict__ joints,
                  float*       __restrict__ out)
{
    const int tid = threadIdx.x;
    const unsigned FULL = 0xffffffffu;

    // ======================= GATHER role (blocks 16..287) ==================
    if (blockIdx.x >= BATCH) {
        const int lb = blockIdx.x - BATCH;
        const int b  = lb / GBPI;
        const int t  = (lb % GBPI) * BT + tid;
        if (t < EPI) {
            const int jl = t / AD;           // joint within image
            const int d  = t % AD;
            const int jj = b * JPI + jl;

            const int idx = __ldg(&joints[jj * 2 + 0]);
            const int vis = __ldg(&joints[jj * 2 + 1]);

            float v = 0.0f;
            if (vis > 0) {
                int off = idx % RR;
                if (off < 0) off += RR;
                const int x = off % RES;     // first spatial axis (torch convention)
                const int y = off / RES;
                v = __ldg(tags + (size_t)b * AD * RR + (size_t)d * RR
                               + (size_t)x * RES + y);
            }
            g_scratch[(size_t)jj * ROWP + d] = v;
        }
        __syncthreads();
        if (tid == 0) {
            __threadfence();                 // publish scratch writes
            atomicAdd(&g_done[b], 1u);
        }
        return;
    }

    // ======================= REDUCE role (blocks 0..15) ====================
    const int b = blockIdx.x;

    __shared__ float t_s[MP][NJ][AD];
    __shared__ float sqv[MP][NJ];
    __shared__ float validf[MP][NJ];
    __shared__ float safe_cnt[MP];
    __shared__ float pullp[MP];
    __shared__ float pv[MP];
    __shared__ float mean_s[MP][AD];
    __shared__ float ntags_s;
    __shared__ float push_acc;

    if (tid == 0) {
        push_acc = 0.0f;
        // wait for this image's 17 producer CTAs
        while (atomicAdd(&g_done[b], 0u) < (unsigned)GBPI) { }
        g_done[b] = 0u;                      // reset for next graph replay
        __threadfence();                     // acquire
    }
    __syncthreads();

    const int* jt_b = joints + b * JPI * 2;

    // ---- per-joint: 4x float4 + 1 scalar from padded scratch ----
    if (tid < JPI) {
        const int m = tid / NJ;
        const int j = tid % NJ;
        const int vis = jt_b[tid * 2 + 1];
        const float valid = (vis > 0) ? 1.0f : 0.0f;

        const float4* p4 = (const float4*)(g_scratch + ((size_t)(b * JPI + tid)) * ROWP);
        float4 r0 = __ldg(p4 + 0);
        float4 r1 = __ldg(p4 + 1);
        float4 r2 = __ldg(p4 + 2);
        float4 r3 = __ldg(p4 + 3);
        float  rl = __ldg((const float*)(p4 + 4));

        float va[AD] = { r0.x, r0.y, r0.z, r0.w,
                         r1.x, r1.y, r1.z, r1.w,
                         r2.x, r2.y, r2.z, r2.w,
                         r3.x, r3.y, r3.z, r3.w, rl };

        float s1 = 0.0f, s2 = 0.0f;
        #pragma unroll
        for (int d = 0; d < AD; d++) {
            s1 += va[d];
            s2 += va[d] * va[d];
            t_s[m][j][d] = va[d];            // already masked by gather
        }
        // valid * sum_{d1,d2}(t_d1 - t_d2)^2 = valid * (2*D*S2 - 2*S1^2)
        sqv[m][j]    = valid * (2.0f * (float)AD * s2 - 2.0f * s1 * s1);
        validf[m][j] = valid;
    }
    __syncthreads();

    // ---- per-person counts + pull_p ----
    if (tid < MP) {
        const int m = tid;
        float cnt = 0.0f, sq = 0.0f;
        #pragma unroll
        for (int j = 0; j < NJ; j++) {
            cnt += validf[m][j];
            sq  += sqv[m][j];
        }
        float scn = fmaxf(cnt, 1.0f);
        safe_cnt[m] = scn;
        float person_valid = (cnt > 0.0f) ? 1.0f : 0.0f;
        pv[m]    = person_valid;
        pullp[m] = person_valid * sq / ((float)(AD * AD) * scn);
    }
    __syncthreads();

    // ---- per-person mean tag: one thread per (m,d) ----
    if (tid < MP * AD) {
        const int m = tid / AD;
        const int d = tid % AD;
        float s = 0.0f;
        #pragma unroll
        for (int j = 0; j < NJ; j++) s += t_s[m][j][d];
        mean_s[m][d] = s / safe_cnt[m];
    }

    // ---- n_tags + pull (warp 0, parallel with mean computation above) ----
    if (tid < 32) {
        float nt = (tid < MP) ? pv[tid]    : 0.0f;
        float pl = (tid < MP) ? pullp[tid] : 0.0f;
        #pragma unroll
        for (int o = 16; o > 0; o >>= 1) {
            nt += __shfl_down_sync(FULL, nt, o);
            pl += __shfl_down_sync(FULL, pl, o);
        }
        if (tid == 0) {
            ntags_s = nt;
            out[BATCH + b] = pl / fmaxf(nt, 1.0f);   // pull[16]
        }
    }
    __syncthreads();

    // ---- push: 900 ordered pairs (diagonal included), direct indexing ----
    float acc = 0.0f;
    #pragma unroll
    for (int p = tid; p < MP * MP; p += BT) {
        const int m1 = p / MP;
        const int m2 = p % MP;
        const float w = pv[m1] * pv[m2];
        if (w != 0.0f) {
            float s = 0.0f;
            #pragma unroll
            for (int d = 0; d < AD; d++) {
                float df = mean_s[m1][d] - mean_s[m2][d];
                s += __expf(-df * df);
            }
            acc += s * (1.0f / (float)AD);
        }
    }
    #pragma unroll
    for (int o = 16; o > 0; o >>= 1)
        acc += __shfl_down_sync(FULL, acc, o);
    if ((tid & 31) == 0) atomicAdd(&push_acc, acc);
    __syncthreads();

    if (tid == 0) {
        const float nt = ntags_s;
        const float denom = fmaxf(nt, 1.0f);
        out[b] = (nt >= 2.0f) ? (push_acc / (denom * denom)) : 0.0f;  // push[16]
    }
}

extern "C" void kernel_launch(void* const* d_in, const int* in_sizes, int n_in,
                              void* d_out, int out_size)
{
    const float* tags   = (const float*)d_in[0];
    const int*   joints = (const int*)d_in[1];
    float*       out    = (float*)d_out;

    ae_onekernel<<<GRID_CTAS, BT>>>(tags, joints, out);
}